// round 8
// baseline (speedup 1.0000x reference)
#include <cuda_runtime.h>
#include <cuda_bf16.h>

// ChamferDistance: B=8, N=4096, D=3.
// Round 8: algorithmic pivot. Brute force hit a ~84K-cycle issue-stall wall
// (fma demand 42.5K, issue ~55%, nothing saturated). Replace with a 1D
// z-bucket grid: bucket-sort both clouds by z (counting sort, 512 buckets),
// then each query scans targets in expanding bucket rings with an exact
// bucket-edge early-exit bound -> ~400 candidates instead of 4096 (~10x less
// work). Queries processed in sorted order so warp lanes are z-adjacent and
// candidate loads are warp-uniform (single 16B sector, L1-resident).
// Min over a fixed candidate set is order-free -> exact result.

#define CD_B 8
#define CD_N 4096
#define CD_NCLOUD 16                   // 8 batches x 2 clouds
#define CD_NB 512                      // z buckets
#define CD_ZMIN (-6.0f)
#define CD_ZW (12.0f / CD_NB)
#define CD_INVZW (CD_NB / 12.0f)
#define CD_QTPB 256
#define CD_QBLKX (CD_N / CD_QTPB)      // 16
#define CD_NPART (CD_QBLKX * CD_B * 2) // 256

__device__ int    g_cnt[CD_NCLOUD][CD_NB];
__device__ int    g_start[CD_NCLOUD][CD_NB];
__device__ int    g_cur[CD_NCLOUD][CD_NB];
__device__ float4 g_sorted[CD_NCLOUD][CD_N];
__device__ float  g_part[CD_NPART];
__device__ unsigned int g_fcnt;

__device__ __forceinline__ int z_bucket(float z) {
    int bk = (int)((z - CD_ZMIN) * CD_INVZW);
    return max(0, min(CD_NB - 1, bk));
}

__device__ __forceinline__ const float* point_ptr(const float* p1, const float* p2,
                                                  int cloud, int i) {
    return (cloud < CD_B) ? p1 + ((size_t)cloud * CD_N + i) * 3
                          : p2 + ((size_t)(cloud - CD_B) * CD_N + i) * 3;
}

// K1: zero histogram.
__global__ void cd_zero_kernel() {
    g_cnt[blockIdx.x][threadIdx.x] = 0;
}

// K2: histogram by z bucket.
__global__ void cd_hist_kernel(const float* __restrict__ p1,
                               const float* __restrict__ p2) {
    int t = blockIdx.x * blockDim.x + threadIdx.x;
    int cloud = t >> 12;
    int i = t & (CD_N - 1);
    const float* p = point_ptr(p1, p2, cloud, i);
    atomicAdd(&g_cnt[cloud][z_bucket(p[2])], 1);
}

// K3: per-cloud exclusive scan of 512 counts (one block per cloud).
__global__ void cd_scan_kernel() {
    __shared__ int s[CD_NB];
    const int c = blockIdx.x;
    const int t = threadIdx.x;
    int v = g_cnt[c][t];
    s[t] = v;
    __syncthreads();
    // Hillis-Steele inclusive scan.
    #pragma unroll
    for (int off = 1; off < CD_NB; off <<= 1) {
        int add = (t >= off) ? s[t - off] : 0;
        __syncthreads();
        s[t] += add;
        __syncthreads();
    }
    int excl = s[t] - v;
    g_start[c][t] = excl;
    g_cur[c][t]   = excl;
}

// K4: scatter points into bucket-sorted order as {x, y, z, |p|^2}.
__global__ void cd_scatter_kernel(const float* __restrict__ p1,
                                  const float* __restrict__ p2) {
    int t = blockIdx.x * blockDim.x + threadIdx.x;
    int cloud = t >> 12;
    int i = t & (CD_N - 1);
    const float* p = point_ptr(p1, p2, cloud, i);
    float x = p[0], y = p[1], z = p[2];
    int pos = atomicAdd(&g_cur[cloud][z_bucket(z)], 1);
    g_sorted[cloud][pos] = make_float4(x, y, z, x * x + y * y + z * z);
}

// K5: expanding-ring NN query + reduction.
__global__ __launch_bounds__(CD_QTPB)
void cd_query_kernel(float* __restrict__ out) {
    __shared__ float red[CD_QTPB];
    __shared__ int s_flag;

    const int tid = threadIdx.x;
    const int b   = blockIdx.y;
    const int dir = blockIdx.z;
    const int qc  = dir ? (CD_B + b) : b;          // query cloud
    const int tc  = dir ? b : (CD_B + b);          // target cloud

    const int i = blockIdx.x * CD_QTPB + tid;
    const float4 q = g_sorted[qc][i];
    const float nx0 = -2.0f * q.x;
    const float nx1 = -2.0f * q.y;
    const float nx2 = -2.0f * q.z;

    const int kb = z_bucket(q.z);
    int cl = __shfl_sync(0xffffffffu, kb, 0);      // sorted -> lane0 = min bucket
    int ch = __shfl_sync(0xffffffffu, kb, 31);     // lane31 = max bucket

    float bestR = 3.402823466e38f;                 // running min of (|t|^2 - 2 q.t)

    // Ring 0: the warp's own bucket span.
    for (int k = cl; k <= ch; k++) {
        const int s = g_start[tc][k];
        const int e = s + g_cnt[tc][k];
        #pragma unroll 4
        for (int j = s; j < e; j++) {
            float4 tp = g_sorted[tc][j];           // warp-uniform load
            float d = fmaf(nx0, tp.x, fmaf(nx1, tp.y, fmaf(nx2, tp.z, tp.w)));
            bestR = fminf(bestR, d);
        }
    }

    // Expanding rings with exact bucket-edge early exit.
    while (true) {
        float dl = (cl == 0) ? 1e30f : q.z - (CD_ZMIN + (float)cl * CD_ZW);
        float dr = (ch == CD_NB - 1) ? 1e30f : (CD_ZMIN + (float)(ch + 1) * CD_ZW) - q.z;
        float lb = fminf(dl, dr);
        float cur = fmaxf(bestR + q.w, 0.0f);
        bool done = (cur <= lb * lb);
        if (__all_sync(0xffffffffu, done)) break;
        if (cl == 0 && ch == CD_NB - 1) break;     // everything scanned

        if (cl > 0) {
            cl--;
            const int s = g_start[tc][cl];
            const int e = s + g_cnt[tc][cl];
            #pragma unroll 4
            for (int j = s; j < e; j++) {
                float4 tp = g_sorted[tc][j];
                float d = fmaf(nx0, tp.x, fmaf(nx1, tp.y, fmaf(nx2, tp.z, tp.w)));
                bestR = fminf(bestR, d);
            }
        }
        if (ch < CD_NB - 1) {
            ch++;
            const int s = g_start[tc][ch];
            const int e = s + g_cnt[tc][ch];
            #pragma unroll 4
            for (int j = s; j < e; j++) {
                float4 tp = g_sorted[tc][j];
                float d = fmaf(nx0, tp.x, fmaf(nx1, tp.y, fmaf(nx2, tp.z, tp.w)));
                bestR = fminf(bestR, d);
            }
        }
    }

    float val = fmaxf(bestR + q.w, 0.0f);          // min_j ||q - t_j||^2

    // Deterministic fixed-order block sum.
    red[tid] = val;
    __syncthreads();
    #pragma unroll
    for (int s = CD_QTPB / 2; s > 0; s >>= 1) {
        if (tid < s) red[tid] += red[tid + s];
        __syncthreads();
    }

    if (tid == 0) {
        const int idx = (dir * CD_B + b) * CD_QBLKX + blockIdx.x;
        g_part[idx] = red[0];
        __threadfence();
        unsigned int t = atomicAdd(&g_fcnt, 1u);
        s_flag = (t == CD_NPART - 1);
    }
    __syncthreads();

    if (s_flag) {
        float v = (tid < CD_NPART) ? g_part[tid] : 0.0f;
        red[tid] = v;
        __syncthreads();
        #pragma unroll
        for (int s = CD_QTPB / 2; s > 0; s >>= 1) {
            if (tid < s) red[tid] += red[tid + s];
            __syncthreads();
        }
        if (tid == 0) {
            out[0] = red[0] * (1.0f / ((float)CD_B * (float)CD_N));
            g_fcnt = 0;                            // reset for graph replay
        }
    }
}

extern "C" void kernel_launch(void* const* d_in, const int* in_sizes, int n_in,
                              void* d_out, int out_size) {
    (void)in_sizes; (void)n_in; (void)out_size;
    const float* p1 = (const float*)d_in[0];
    const float* p2 = (const float*)d_in[1];
    float* out = (float*)d_out;

    cd_zero_kernel<<<CD_NCLOUD, CD_NB>>>();
    cd_hist_kernel<<<(CD_NCLOUD * CD_N) / 256, 256>>>(p1, p2);
    cd_scan_kernel<<<CD_NCLOUD, CD_NB>>>();
    cd_scatter_kernel<<<(CD_NCLOUD * CD_N) / 256, 256>>>(p1, p2);
    dim3 qgrid(CD_QBLKX, CD_B, 2);
    cd_query_kernel<<<qgrid, CD_QTPB>>>(out);
}

// round 9
// speedup vs baseline: 1.4587x; 1.4587x over previous
#include <cuda_runtime.h>
#include <cuda_bf16.h>

// ChamferDistance: B=8, N=4096, D=3.
// Round 9: keep the z-bucket grid (round-8 pruning was correct: exact result,
// ~10x fewer candidates) but fix the query kernel's memory structure. Round 8
// scanned candidates with MLP=1 dependent global loads against a cold L1
// (flushed per launch) -> ~234cyc exposed per candidate. Now each 128-query
// block STAGES its whole candidate window (block span +- R buckets) into smem
// with coalesced high-MLP float4 loads, then warps scan their sub-window from
// smem (broadcast LDS, pipelined). Exactness: bucket-edge bound per lane; rare
// unsatisfied lanes fall back to global expanding rings.

#define CD_B 8
#define CD_N 4096
#define CD_NCLOUD 16
#define CD_NB 512
#define CD_ZMIN (-6.0f)
#define CD_ZW (12.0f / CD_NB)
#define CD_INVZW (CD_NB / 12.0f)
#define CD_R 10                          // margin buckets (~0.234 in z)
#define CD_CAP 2048                      // staged window cap (32KB of float4)
#define CD_QTPB 128
#define CD_QBLKX (CD_N / CD_QTPB)        // 32
#define CD_NPART (CD_QBLKX * CD_B * 2)   // 512

__device__ int    g_cnt[CD_NCLOUD][CD_NB];
__device__ int    g_start[CD_NCLOUD][CD_NB];
__device__ int    g_cur[CD_NCLOUD][CD_NB];
__device__ float4 g_sorted[CD_NCLOUD][CD_N];
__device__ float  g_part[CD_NPART];
__device__ unsigned int g_fcnt;

__device__ __forceinline__ int z_bucket(float z) {
    int bk = (int)((z - CD_ZMIN) * CD_INVZW);
    return max(0, min(CD_NB - 1, bk));
}

__device__ __forceinline__ const float* point_ptr(const float* p1, const float* p2,
                                                  int cloud, int i) {
    return (cloud < CD_B) ? p1 + ((size_t)cloud * CD_N + i) * 3
                          : p2 + ((size_t)(cloud - CD_B) * CD_N + i) * 3;
}

__global__ void cd_zero_kernel() {
    g_cnt[blockIdx.x][threadIdx.x] = 0;
}

__global__ void cd_hist_kernel(const float* __restrict__ p1,
                               const float* __restrict__ p2) {
    int t = blockIdx.x * blockDim.x + threadIdx.x;
    int cloud = t >> 12;
    int i = t & (CD_N - 1);
    const float* p = point_ptr(p1, p2, cloud, i);
    atomicAdd(&g_cnt[cloud][z_bucket(p[2])], 1);
}

__global__ void cd_scan_kernel() {
    __shared__ int s[CD_NB];
    const int c = blockIdx.x;
    const int t = threadIdx.x;
    int v = g_cnt[c][t];
    s[t] = v;
    __syncthreads();
    #pragma unroll
    for (int off = 1; off < CD_NB; off <<= 1) {
        int add = (t >= off) ? s[t - off] : 0;
        __syncthreads();
        s[t] += add;
        __syncthreads();
    }
    int excl = s[t] - v;
    g_start[c][t] = excl;
    g_cur[c][t]   = excl;
}

__global__ void cd_scatter_kernel(const float* __restrict__ p1,
                                  const float* __restrict__ p2) {
    int t = blockIdx.x * blockDim.x + threadIdx.x;
    int cloud = t >> 12;
    int i = t & (CD_N - 1);
    const float* p = point_ptr(p1, p2, cloud, i);
    float x = p[0], y = p[1], z = p[2];
    int pos = atomicAdd(&g_cur[cloud][z_bucket(z)], 1);
    g_sorted[cloud][pos] = make_float4(x, y, z, x * x + y * y + z * z);
}

__global__ __launch_bounds__(CD_QTPB)
void cd_query_kernel(float* __restrict__ out) {
    __shared__ float4 s_pts[CD_CAP];
    __shared__ int    s_off[CD_NB + 1];
    __shared__ float  red[CD_QTPB];
    __shared__ int    s_wlo, s_whi, s_base, s_cnt, s_flag;

    const int tid = threadIdx.x;
    const int b   = blockIdx.y;
    const int dir = blockIdx.z;
    const int qc  = dir ? (CD_B + b) : b;
    const int tc  = dir ? b : (CD_B + b);
    const int qbase = blockIdx.x * CD_QTPB;

    const float4 q = g_sorted[qc][qbase + tid];
    const float nx0 = -2.0f * q.x;
    const float nx1 = -2.0f * q.y;
    const float nx2 = -2.0f * q.z;
    const int kb = z_bucket(q.z);

    // Block window: span of the block's (sorted) queries widened by R buckets.
    if (tid == 0) {
        int bl = z_bucket(g_sorted[qc][qbase].z);
        int bh = z_bucket(g_sorted[qc][qbase + CD_QTPB - 1].z);
        int r = CD_R, lo, hi, base, cnt;
        do {
            lo = max(bl - r, 0);
            hi = min(bh + r, CD_NB - 1);
            base = g_start[tc][lo];
            cnt  = g_start[tc][hi] + g_cnt[tc][hi] - base;
            r--;
        } while (cnt > CD_CAP && r >= 0);
        s_wlo = lo; s_whi = hi; s_base = base; s_cnt = cnt;
    }
    __syncthreads();
    const int wlo = s_wlo, whi = s_whi, wbase = s_base, wcnt = s_cnt;

    // Stage candidate window (coalesced, high MLP) + bucket offsets.
    for (int j = tid; j < wcnt; j += CD_QTPB)
        s_pts[j] = g_sorted[tc][wbase + j];
    const int nbw = whi - wlo + 1;
    for (int k = tid; k < nbw; k += CD_QTPB)
        s_off[k] = g_start[tc][wlo + k] - wbase;
    if (tid == 0) s_off[nbw] = wcnt;
    __syncthreads();

    // Warp sub-window scan from smem.
    int wl = __shfl_sync(0xffffffffu, kb, 0);
    int wh = __shfl_sync(0xffffffffu, kb, 31);
    int a  = max(wl - CD_R, wlo);
    int bE = min(wh + CD_R, whi);
    const int sLo = s_off[a - wlo];
    const int sHi = s_off[bE - wlo + 1];

    float bestR = 3.402823466e38f;
    #pragma unroll 4
    for (int j = sLo; j < sHi; j++) {
        float4 tp = s_pts[j];                        // broadcast LDS
        float d = fmaf(nx0, tp.x, fmaf(nx1, tp.y, fmaf(nx2, tp.z, tp.w)));
        bestR = fminf(bestR, d);
    }

    // Exactness check against the scanned sub-window edges.
    {
        float dl = (a == 0) ? 1e30f : q.z - (CD_ZMIN + (float)a * CD_ZW);
        float dr = (bE == CD_NB - 1) ? 1e30f : (CD_ZMIN + (float)(bE + 1) * CD_ZW) - q.z;
        float lb = fminf(dl, dr);
        float cur = fmaxf(bestR + q.w, 0.0f);
        bool done = (cur <= lb * lb);

        // Rare fallback: expand rings outside [a, bE] from global memory.
        if (!__all_sync(0xffffffffu, done)) {
            int cl = a, ch = bE;
            while (true) {
                dl = (cl == 0) ? 1e30f : q.z - (CD_ZMIN + (float)cl * CD_ZW);
                dr = (ch == CD_NB - 1) ? 1e30f : (CD_ZMIN + (float)(ch + 1) * CD_ZW) - q.z;
                lb = fminf(dl, dr);
                cur = fmaxf(bestR + q.w, 0.0f);
                done = (cur <= lb * lb);
                if (__all_sync(0xffffffffu, done)) break;
                if (cl == 0 && ch == CD_NB - 1) break;

                if (cl > 0) {
                    cl--;
                    const int s = g_start[tc][cl];
                    const int e = s + g_cnt[tc][cl];
                    for (int j = s; j < e; j++) {
                        float4 tp = g_sorted[tc][j];
                        float d = fmaf(nx0, tp.x, fmaf(nx1, tp.y, fmaf(nx2, tp.z, tp.w)));
                        bestR = fminf(bestR, d);
                    }
                }
                if (ch < CD_NB - 1) {
                    ch++;
                    const int s = g_start[tc][ch];
                    const int e = s + g_cnt[tc][ch];
                    for (int j = s; j < e; j++) {
                        float4 tp = g_sorted[tc][j];
                        float d = fmaf(nx0, tp.x, fmaf(nx1, tp.y, fmaf(nx2, tp.z, tp.w)));
                        bestR = fminf(bestR, d);
                    }
                }
            }
        }
    }

    float val = fmaxf(bestR + q.w, 0.0f);

    // Deterministic fixed-order block sum.
    red[tid] = val;
    __syncthreads();
    #pragma unroll
    for (int s = CD_QTPB / 2; s > 0; s >>= 1) {
        if (tid < s) red[tid] += red[tid + s];
        __syncthreads();
    }

    if (tid == 0) {
        const int idx = (dir * CD_B + b) * CD_QBLKX + blockIdx.x;
        g_part[idx] = red[0];
        __threadfence();
        unsigned int t = atomicAdd(&g_fcnt, 1u);
        s_flag = (t == CD_NPART - 1);
    }
    __syncthreads();

    if (s_flag) {
        float acc = 0.0f;
        #pragma unroll
        for (int k = 0; k < CD_NPART / CD_QTPB; k++)
            acc += g_part[k * CD_QTPB + tid];
        red[tid] = acc;
        __syncthreads();
        #pragma unroll
        for (int s = CD_QTPB / 2; s > 0; s >>= 1) {
            if (tid < s) red[tid] += red[tid + s];
            __syncthreads();
        }
        if (tid == 0) {
            out[0] = red[0] * (1.0f / ((float)CD_B * (float)CD_N));
            g_fcnt = 0;                              // reset for graph replay
        }
    }
}

extern "C" void kernel_launch(void* const* d_in, const int* in_sizes, int n_in,
                              void* d_out, int out_size) {
    (void)in_sizes; (void)n_in; (void)out_size;
    const float* p1 = (const float*)d_in[0];
    const float* p2 = (const float*)d_in[1];
    float* out = (float*)d_out;

    cd_zero_kernel<<<CD_NCLOUD, CD_NB>>>();
    cd_hist_kernel<<<(CD_NCLOUD * CD_N) / 256, 256>>>(p1, p2);
    cd_scan_kernel<<<CD_NCLOUD, CD_NB>>>();
    cd_scatter_kernel<<<(CD_NCLOUD * CD_N) / 256, 256>>>(p1, p2);
    dim3 qgrid(CD_QBLKX, CD_B, 2);
    cd_query_kernel<<<qgrid, CD_QTPB>>>(out);
}

// round 10
// speedup vs baseline: 2.4386x; 1.6717x over previous
#include <cuda_runtime.h>
#include <cuda_bf16.h>

// ChamferDistance: B=8, N=4096, D=3.
// Round 10: round-9's residual 100us was the global-memory fallback path:
// tail warps (NN dist >> 10-bucket margin) did serial MLP=1 cold-L1 global
// ring scans (~300cyc/point) and set the wallclock as stragglers. Fix: stage
// the ENTIRE sorted target cloud (4096 float4 = 64KB) in dynamic smem per
// block, so ALL ring expansion hits smem. No global fallback path exists.
// Exact bucket-edge early exit; two min accumulators break the FMNMX chain.

#define CD_B 8
#define CD_N 4096
#define CD_NCLOUD 16
#define CD_NB 512
#define CD_ZMIN (-6.0f)
#define CD_ZW (12.0f / CD_NB)
#define CD_INVZW (CD_NB / 12.0f)
#define CD_QTPB 128
#define CD_QBLKX (CD_N / CD_QTPB)        // 32
#define CD_NPART (CD_QBLKX * CD_B * 2)   // 512

// dynamic smem layout
#define CD_SMEM_PTS_BYTES (CD_N * 16)                 // 65536
#define CD_SMEM_OFF_BYTES ((CD_NB + 1) * 4)           // 2052 -> pad 2064
#define CD_SMEM_TOTAL (CD_SMEM_PTS_BYTES + 2064 + CD_QTPB * 4)

__device__ int    g_cnt[CD_NCLOUD][CD_NB];
__device__ int    g_start[CD_NCLOUD][CD_NB];
__device__ int    g_cur[CD_NCLOUD][CD_NB];
__device__ float4 g_sorted[CD_NCLOUD][CD_N];
__device__ float  g_part[CD_NPART];
__device__ unsigned int g_fcnt;

__device__ __forceinline__ int z_bucket(float z) {
    int bk = (int)((z - CD_ZMIN) * CD_INVZW);
    return max(0, min(CD_NB - 1, bk));
}

__device__ __forceinline__ const float* point_ptr(const float* p1, const float* p2,
                                                  int cloud, int i) {
    return (cloud < CD_B) ? p1 + ((size_t)cloud * CD_N + i) * 3
                          : p2 + ((size_t)(cloud - CD_B) * CD_N + i) * 3;
}

__global__ void cd_zero_kernel() {
    g_cnt[blockIdx.x][threadIdx.x] = 0;
}

__global__ void cd_hist_kernel(const float* __restrict__ p1,
                               const float* __restrict__ p2) {
    int t = blockIdx.x * blockDim.x + threadIdx.x;
    int cloud = t >> 12;
    int i = t & (CD_N - 1);
    const float* p = point_ptr(p1, p2, cloud, i);
    atomicAdd(&g_cnt[cloud][z_bucket(p[2])], 1);
}

__global__ void cd_scan_kernel() {
    __shared__ int s[CD_NB];
    const int c = blockIdx.x;
    const int t = threadIdx.x;
    int v = g_cnt[c][t];
    s[t] = v;
    __syncthreads();
    #pragma unroll
    for (int off = 1; off < CD_NB; off <<= 1) {
        int add = (t >= off) ? s[t - off] : 0;
        __syncthreads();
        s[t] += add;
        __syncthreads();
    }
    int excl = s[t] - v;
    g_start[c][t] = excl;
    g_cur[c][t]   = excl;
}

__global__ void cd_scatter_kernel(const float* __restrict__ p1,
                                  const float* __restrict__ p2) {
    int t = blockIdx.x * blockDim.x + threadIdx.x;
    int cloud = t >> 12;
    int i = t & (CD_N - 1);
    const float* p = point_ptr(p1, p2, cloud, i);
    float x = p[0], y = p[1], z = p[2];
    int pos = atomicAdd(&g_cur[cloud][z_bucket(z)], 1);
    g_sorted[cloud][pos] = make_float4(x, y, z, x * x + y * y + z * z);
}

__global__ __launch_bounds__(CD_QTPB)
void cd_query_kernel(float* __restrict__ out) {
    extern __shared__ char dynsmem[];
    float4* s_pts = reinterpret_cast<float4*>(dynsmem);
    int*    s_off = reinterpret_cast<int*>(dynsmem + CD_SMEM_PTS_BYTES);
    float*  red   = reinterpret_cast<float*>(dynsmem + CD_SMEM_PTS_BYTES + 2064);
    __shared__ int s_flag;

    const int tid = threadIdx.x;
    const int b   = blockIdx.y;
    const int dir = blockIdx.z;
    const int qc  = dir ? (CD_B + b) : b;
    const int tc  = dir ? b : (CD_B + b);
    const int qbase = blockIdx.x * CD_QTPB;

    const float4 q = g_sorted[qc][qbase + tid];
    const float nx0 = -2.0f * q.x;
    const float nx1 = -2.0f * q.y;
    const float nx2 = -2.0f * q.z;
    const int kb = z_bucket(q.z);

    // Stage entire target cloud + bucket offsets (coalesced, high MLP).
    #pragma unroll
    for (int j = tid; j < CD_N; j += CD_QTPB)
        s_pts[j] = g_sorted[tc][j];
    for (int k = tid; k < CD_NB; k += CD_QTPB)
        s_off[k] = g_start[tc][k];
    if (tid == 0) s_off[CD_NB] = CD_N;
    __syncthreads();

    // Warp bucket span (queries are sorted: lane0 min, lane31 max).
    int cl = __shfl_sync(0xffffffffu, kb, 0);
    int ch = __shfl_sync(0xffffffffu, kb, 31);

    float m0 = 3.402823466e38f, m1 = 3.402823466e38f;

    // Ring 0: warp's own span.
    {
        const int s = s_off[cl], e = s_off[ch + 1];
        int j = s;
        #pragma unroll 2
        for (; j + 1 < e; j += 2) {
            float4 t0 = s_pts[j];
            float4 t1 = s_pts[j + 1];
            m0 = fminf(m0, fmaf(nx0, t0.x, fmaf(nx1, t0.y, fmaf(nx2, t0.z, t0.w))));
            m1 = fminf(m1, fmaf(nx0, t1.x, fmaf(nx1, t1.y, fmaf(nx2, t1.z, t1.w))));
        }
        if (j < e) {
            float4 t0 = s_pts[j];
            m0 = fminf(m0, fmaf(nx0, t0.x, fmaf(nx1, t0.y, fmaf(nx2, t0.z, t0.w))));
        }
    }

    // Expanding rings, entirely in smem, exact bucket-edge bound.
    while (true) {
        float dl = (cl == 0) ? 1e30f : q.z - (CD_ZMIN + (float)cl * CD_ZW);
        float dr = (ch == CD_NB - 1) ? 1e30f : (CD_ZMIN + (float)(ch + 1) * CD_ZW) - q.z;
        float lb = fminf(dl, dr);
        float cur = fmaxf(fminf(m0, m1) + q.w, 0.0f);
        bool done = (cur <= lb * lb);
        if (__all_sync(0xffffffffu, done)) break;
        if (cl == 0 && ch == CD_NB - 1) break;

        int nl = (cl > 0) ? cl - 1 : cl;
        int nh = (ch < CD_NB - 1) ? ch + 1 : ch;
        // Scan the two new bucket slivers (contiguous ranges in smem).
        if (nl < cl) {
            const int s = s_off[nl], e = s_off[cl];
            for (int j = s; j < e; j++) {
                float4 t0 = s_pts[j];
                m0 = fminf(m0, fmaf(nx0, t0.x, fmaf(nx1, t0.y, fmaf(nx2, t0.z, t0.w))));
            }
        }
        if (nh > ch) {
            const int s = s_off[ch + 1], e = s_off[nh + 1];
            for (int j = s; j < e; j++) {
                float4 t1 = s_pts[j];
                m1 = fminf(m1, fmaf(nx0, t1.x, fmaf(nx1, t1.y, fmaf(nx2, t1.z, t1.w))));
            }
        }
        cl = nl; ch = nh;
    }

    float val = fmaxf(fminf(m0, m1) + q.w, 0.0f);

    // Deterministic fixed-order block sum.
    red[tid] = val;
    __syncthreads();
    #pragma unroll
    for (int s = CD_QTPB / 2; s > 0; s >>= 1) {
        if (tid < s) red[tid] += red[tid + s];
        __syncthreads();
    }

    if (tid == 0) {
        const int idx = (dir * CD_B + b) * CD_QBLKX + blockIdx.x;
        g_part[idx] = red[0];
        __threadfence();
        unsigned int t = atomicAdd(&g_fcnt, 1u);
        s_flag = (t == CD_NPART - 1);
    }
    __syncthreads();

    if (s_flag) {
        float acc = 0.0f;
        #pragma unroll
        for (int k = 0; k < CD_NPART / CD_QTPB; k++)
            acc += g_part[k * CD_QTPB + tid];
        red[tid] = acc;
        __syncthreads();
        #pragma unroll
        for (int s = CD_QTPB / 2; s > 0; s >>= 1) {
            if (tid < s) red[tid] += red[tid + s];
            __syncthreads();
        }
        if (tid == 0) {
            out[0] = red[0] * (1.0f / ((float)CD_B * (float)CD_N));
            g_fcnt = 0;                              // reset for graph replay
        }
    }
}

extern "C" void kernel_launch(void* const* d_in, const int* in_sizes, int n_in,
                              void* d_out, int out_size) {
    (void)in_sizes; (void)n_in; (void)out_size;
    const float* p1 = (const float*)d_in[0];
    const float* p2 = (const float*)d_in[1];
    float* out = (float*)d_out;

    // Raise the dynamic smem cap (idempotent; not a stream/allocation call).
    static bool attr_set = false;
    if (!attr_set) {
        cudaFuncSetAttribute(cd_query_kernel,
                             cudaFuncAttributeMaxDynamicSharedMemorySize,
                             CD_SMEM_TOTAL);
        attr_set = true;
    }

    cd_zero_kernel<<<CD_NCLOUD, CD_NB>>>();
    cd_hist_kernel<<<(CD_NCLOUD * CD_N) / 256, 256>>>(p1, p2);
    cd_scan_kernel<<<CD_NCLOUD, CD_NB>>>();
    cd_scatter_kernel<<<(CD_NCLOUD * CD_N) / 256, 256>>>(p1, p2);
    dim3 qgrid(CD_QBLKX, CD_B, 2);
    cd_query_kernel<<<qgrid, CD_QTPB, CD_SMEM_TOTAL>>>(out);
}